// round 4
// baseline (speedup 1.0000x reference)
#include <cuda_runtime.h>
#include <math.h>

#define N_RAYS   32768
#define S_USED   115        // only samples 0..114 contribute
#define GD       128
#define NCH      27

__global__ __launch_bounds__(128, 6)
void rf_render_kernel(const float* __restrict__ xin,
                      const float* __restrict__ din,
                      const float* __restrict__ tminp,
                      const float* __restrict__ tmaxp,
                      const float* __restrict__ grid,
                      const float* __restrict__ opacity,
                      float* __restrict__ out)
{
    __shared__ float coef[S_USED][29];
    __shared__ float shs[9];
    __shared__ float wsum[4];
    __shared__ float red[4][3];

    const int ray  = blockIdx.x;
    const int tid  = threadIdx.x;
    const int lane = tid & 31;
    const int warp = tid >> 5;

    const float dx = din[ray*3+0];
    const float dy = din[ray*3+1];
    const float dz = din[ray*3+2];
    const float ox = xin[ray*3+0];
    const float oy = xin[ray*3+1];
    const float oz = xin[ray*3+2];
    const float t0 = tminp[ray];
    const float range = tmaxp[ray] - t0;

    if (tid < 9) {
        float v = 0.f;
        switch (tid) {
            case 0: v = 0.28209479177387814f; break;
            case 1: v = -0.4886025119029199f * dy; break;
            case 2: v =  0.4886025119029199f * dz; break;
            case 3: v = -0.4886025119029199f * dx; break;
            case 4: v =  1.0925484305920792f * dx * dy; break;
            case 5: v = -1.0925484305920792f * dy * dz; break;
            case 6: v =  0.31539156525252005f * (2.f*dz*dz - dx*dx - dy*dy); break;
            case 7: v = -1.0925484305920792f * dx * dz; break;
            case 8: v =  0.5462742152960396f * (dx*dx - dy*dy); break;
        }
        shs[tid] = v;
    }
    __syncthreads();

    const float mysh = (lane < 27) ? shs[lane % 9] : 1.f;

    // lanes 0..26 -> grid channel `lane`; lanes 27..31 -> opacity (dupes discarded)
    const float* bptr  = (lane < NCH) ? (grid + lane) : opacity;
    const int   stride = (lane < NCH) ? NCH : 1;

    const int s1     = stride;        // z+1 step (scaled)
    const int s128   = stride << 7;   // y+1 step
    const int s16384 = stride << 14;  // x+1 step

    // corner pointers: k = (x<<2)|(y<<1)|z
    const float* p[8];
    p[0] = bptr;
    p[1] = bptr + s1;
    p[2] = bptr + s128;
    p[3] = bptr + s128 + s1;
    p[4] = bptr + s16384;
    p[5] = bptr + s16384 + s1;
    p[6] = bptr + s16384 + s128;
    p[7] = bptr + s16384 + s128 + s1;

    // ---- phase 1: warp takes contiguous sample chunk; cache 8 corners ----
    const int chunk  = (S_USED + 3) / 4;          // 29
    const int sbeg   = warp * chunk;
    const int send   = min(sbeg + chunk, S_USED);

    float v[8];
    int bprev = 0x40000000;   // impossible

    for (int s = sbeg; s < send; s++) {
        float t  = fmaf(range, fmaf((float)s, 1.f/128.f, 0.05f), t0);
        float px = fminf(fmaxf(fmaf(t, dx, ox), 0.f), 126.9999f);
        float py = fminf(fmaxf(fmaf(t, dy, oy), 0.f), 126.9999f);
        float pz = fminf(fmaxf(fmaf(t, dz, oz), 0.f), 126.9999f);

        float fx0 = floorf(px), fy0 = floorf(py), fz0 = floorf(pz);
        int ix0 = (int)fx0, iy0 = (int)fy0, iz0 = (int)fz0;
        float fx = px - fx0, fy = py - fy0, fz = pz - fz0;

        int b = ((ix0 << 14) + (iy0 << 7) + iz0) * stride;
        int db = b - bprev;

        if (db != 0) {
            // db is warp-uniform in truth value: both sides scale with stride.
            if (db == s1) {            // z+1: keep z1 side as new z0
                v[0]=v[1]; v[2]=v[3]; v[4]=v[5]; v[6]=v[7];
                v[1]=__ldg(p[1]+b); v[3]=__ldg(p[3]+b); v[5]=__ldg(p[5]+b); v[7]=__ldg(p[7]+b);
            } else if (db == -s1) {    // z-1
                v[1]=v[0]; v[3]=v[2]; v[5]=v[4]; v[7]=v[6];
                v[0]=__ldg(p[0]+b); v[2]=__ldg(p[2]+b); v[4]=__ldg(p[4]+b); v[6]=__ldg(p[6]+b);
            } else if (db == s128) {   // y+1
                v[0]=v[2]; v[1]=v[3]; v[4]=v[6]; v[5]=v[7];
                v[2]=__ldg(p[2]+b); v[3]=__ldg(p[3]+b); v[6]=__ldg(p[6]+b); v[7]=__ldg(p[7]+b);
            } else if (db == -s128) {  // y-1
                v[2]=v[0]; v[3]=v[1]; v[6]=v[4]; v[7]=v[5];
                v[0]=__ldg(p[0]+b); v[1]=__ldg(p[1]+b); v[4]=__ldg(p[4]+b); v[5]=__ldg(p[5]+b);
            } else if (db == s16384) { // x+1
                v[0]=v[4]; v[1]=v[5]; v[2]=v[6]; v[3]=v[7];
                v[4]=__ldg(p[4]+b); v[5]=__ldg(p[5]+b); v[6]=__ldg(p[6]+b); v[7]=__ldg(p[7]+b);
            } else if (db == -s16384) { // x-1
                v[4]=v[0]; v[5]=v[1]; v[6]=v[2]; v[7]=v[3];
                v[0]=__ldg(p[0]+b); v[1]=__ldg(p[1]+b); v[2]=__ldg(p[2]+b); v[3]=__ldg(p[3]+b);
            } else {                   // general: reload all 8
                #pragma unroll
                for (int k = 0; k < 8; k++) v[k] = __ldg(p[k] + b);
            }
            bprev = b;
        }

        float gx0 = 1.f - fx, gy0 = 1.f - fy, gz0 = 1.f - fz;
        float acc;
        acc  = (gx0*gy0*gz0) * v[0];
        acc  = fmaf(gx0*gy0*fz , v[1], acc);
        acc  = fmaf(gx0*fy *gz0, v[2], acc);
        acc  = fmaf(gx0*fy *fz , v[3], acc);
        acc  = fmaf(fx *gy0*gz0, v[4], acc);
        acc  = fmaf(fx *gy0*fz , v[5], acc);
        acc  = fmaf(fx *fy *gz0, v[6], acc);
        acc  = fmaf(fx *fy *fz , v[7], acc);

        if (lane < 28)
            coef[s][lane] = acc * mysh;
    }
    __syncthreads();

    // ---- phase 2: thread-per-sample dot + transmittance scan + reduce ----
    float dts = 0.f;
    float c0 = 0.f, c1 = 0.f, c2 = 0.f;
    if (tid < S_USED) {
        const float* row = coef[tid];
        #pragma unroll
        for (int j = 0; j < 9; j++) {
            c0 += row[j];
            c1 += row[9 + j];
            c2 += row[18 + j];
        }
        float op = fminf(fmaxf(row[27], 0.f), 100000.f);
        float delta = range * (1.f / 128.f);
        dts = -delta * op;
    }

    float xs = dts;
    #pragma unroll
    for (int off = 1; off < 32; off <<= 1) {
        float n = __shfl_up_sync(0xffffffffu, xs, off);
        if (lane >= off) xs += n;
    }
    if (lane == 31) wsum[warp] = xs;
    __syncthreads();
    float offacc = 0.f;
    #pragma unroll
    for (int w = 0; w < 4; w++)
        if (w < warp) offacc += wsum[w];
    float cum = offacc + xs - dts;     // exclusive prefix

    float r0 = 0.f, r1 = 0.f, r2 = 0.f;
    if (tid < S_USED) {
        float wgt = expf(cum) * (1.f - expf(dts));
        c0 = fminf(fmaxf(c0 + 0.5f, 0.f), 100000.f);
        c1 = fminf(fmaxf(c1 + 0.5f, 0.f), 100000.f);
        c2 = fminf(fmaxf(c2 + 0.5f, 0.f), 100000.f);
        r0 = wgt * c0;  r1 = wgt * c1;  r2 = wgt * c2;
    }

    #pragma unroll
    for (int off = 16; off > 0; off >>= 1) {
        r0 += __shfl_down_sync(0xffffffffu, r0, off);
        r1 += __shfl_down_sync(0xffffffffu, r1, off);
        r2 += __shfl_down_sync(0xffffffffu, r2, off);
    }
    if (lane == 0) {
        red[warp][0] = r0;  red[warp][1] = r1;  red[warp][2] = r2;
    }
    __syncthreads();
    if (tid == 0) {
        out[ray*3+0] = red[0][0] + red[1][0] + red[2][0] + red[3][0];
        out[ray*3+1] = red[0][1] + red[1][1] + red[2][1] + red[3][1];
        out[ray*3+2] = red[0][2] + red[1][2] + red[2][2] + red[3][2];
    }
}

extern "C" void kernel_launch(void* const* d_in, const int* in_sizes, int n_in,
                              void* d_out, int out_size)
{
    const float* x       = (const float*)d_in[0];
    const float* d       = (const float*)d_in[1];
    const float* tmin    = (const float*)d_in[2];
    const float* tmax    = (const float*)d_in[3];
    const float* grid    = (const float*)d_in[4];
    const float* opacity = (const float*)d_in[5];
    float* out = (float*)d_out;

    rf_render_kernel<<<N_RAYS, 128>>>(x, d, tmin, tmax, grid, opacity, out);
}

// round 5
// speedup vs baseline: 1.1626x; 1.1626x over previous
#include <cuda_runtime.h>
#include <math.h>

#define N_RAYS   32768
#define S_USED   115        // only samples 0..114 contribute
#define GD       128
#define NCH      27

__global__ __launch_bounds__(128, 7)
void rf_render_kernel(const float* __restrict__ xin,
                      const float* __restrict__ din,
                      const float* __restrict__ tminp,
                      const float* __restrict__ tmaxp,
                      const float* __restrict__ grid,
                      const float* __restrict__ opacity,
                      float* __restrict__ out)
{
    __shared__ float coef[S_USED][29];
    __shared__ float shs[9];
    __shared__ float wsum[4];
    __shared__ float red[4][3];

    const int ray  = blockIdx.x;
    const int tid  = threadIdx.x;
    const int lane = tid & 31;
    const int warp = tid >> 5;

    const float dx = din[ray*3+0];
    const float dy = din[ray*3+1];
    const float dz = din[ray*3+2];
    const float ox = xin[ray*3+0];
    const float oy = xin[ray*3+1];
    const float oz = xin[ray*3+2];
    const float t0 = tminp[ray];
    const float range = tmaxp[ray] - t0;

    if (tid < 9) {
        float v = 0.f;
        switch (tid) {
            case 0: v = 0.28209479177387814f; break;
            case 1: v = -0.4886025119029199f * dy; break;
            case 2: v =  0.4886025119029199f * dz; break;
            case 3: v = -0.4886025119029199f * dx; break;
            case 4: v =  1.0925484305920792f * dx * dy; break;
            case 5: v = -1.0925484305920792f * dy * dz; break;
            case 6: v =  0.31539156525252005f * (2.f*dz*dz - dx*dx - dy*dy); break;
            case 7: v = -1.0925484305920792f * dx * dz; break;
            case 8: v =  0.5462742152960396f * (dx*dx - dy*dy); break;
        }
        shs[tid] = v;
    }
    __syncthreads();

    const float mysh = (lane < 27) ? shs[lane % 9] : 1.f;

    // lanes 0..26 -> grid channel `lane`; lanes 27..31 -> opacity (dupes discarded)
    const float* bptr  = (lane < NCH) ? (grid + lane) : opacity;
    const int   stride = (lane < NCH) ? NCH : 1;

    const int s1     = stride;        // z+1 step (scaled)
    const int s128   = stride << 7;   // y+1 step
    const int s16384 = stride << 14;  // x+1 step

    // corner pointers: k = (x<<2)|(y<<1)|z
    const float* p[8];
    p[0] = bptr;
    p[1] = bptr + s1;
    p[2] = bptr + s128;
    p[3] = bptr + s128 + s1;
    p[4] = bptr + s16384;
    p[5] = bptr + s16384 + s1;
    p[6] = bptr + s16384 + s128;
    p[7] = bptr + s16384 + s128 + s1;

    // ---- phase 1: contiguous sample chunk per warp; reuse corners when the
    //      base voxel is unchanged (≈50% of steps), else reload all 8 ----
    const int chunk  = (S_USED + 3) / 4;          // 29
    const int sbeg   = warp * chunk;
    const int send   = min(sbeg + chunk, S_USED);

    float v[8];
    int bprev = 0x40000000;   // impossible

    for (int s = sbeg; s < send; s++) {
        float t  = fmaf(range, fmaf((float)s, 1.f/128.f, 0.05f), t0);
        float px = fminf(fmaxf(fmaf(t, dx, ox), 0.f), 126.9999f);
        float py = fminf(fmaxf(fmaf(t, dy, oy), 0.f), 126.9999f);
        float pz = fminf(fmaxf(fmaf(t, dz, oz), 0.f), 126.9999f);

        float fx0 = floorf(px), fy0 = floorf(py), fz0 = floorf(pz);
        int ix0 = (int)fx0, iy0 = (int)fy0, iz0 = (int)fz0;
        float fx = px - fx0, fy = py - fy0, fz = pz - fz0;

        int b = ((ix0 << 14) + (iy0 << 7) + iz0) * stride;

        // warp-uniform predicate: b/bprev both scale with per-lane stride,
        // so (b != bprev) is identical across lanes -> convergent branch.
        if (b != bprev) {
            #pragma unroll
            for (int k = 0; k < 8; k++) v[k] = __ldg(p[k] + b);
            bprev = b;
        }

        float gx0 = 1.f - fx, gy0 = 1.f - fy, gz0 = 1.f - fz;
        float wy0z0 = gy0*gz0, wy0z1 = gy0*fz, wy1z0 = fy*gz0, wy1z1 = fy*fz;

        float acc;
        acc  = (gx0*wy0z0) * v[0];
        acc  = fmaf(gx0*wy0z1, v[1], acc);
        acc  = fmaf(gx0*wy1z0, v[2], acc);
        acc  = fmaf(gx0*wy1z1, v[3], acc);
        acc  = fmaf(fx *wy0z0, v[4], acc);
        acc  = fmaf(fx *wy0z1, v[5], acc);
        acc  = fmaf(fx *wy1z0, v[6], acc);
        acc  = fmaf(fx *wy1z1, v[7], acc);

        if (lane < 28)
            coef[s][lane] = acc * mysh;
    }
    __syncthreads();

    // ---- phase 2: thread-per-sample dot + transmittance scan + reduce ----
    float dts = 0.f;
    float c0 = 0.f, c1 = 0.f, c2 = 0.f;
    if (tid < S_USED) {
        const float* row = coef[tid];
        #pragma unroll
        for (int j = 0; j < 9; j++) {
            c0 += row[j];
            c1 += row[9 + j];
            c2 += row[18 + j];
        }
        float op = fminf(fmaxf(row[27], 0.f), 100000.f);
        float delta = range * (1.f / 128.f);
        dts = -delta * op;
    }

    float xs = dts;
    #pragma unroll
    for (int off = 1; off < 32; off <<= 1) {
        float n = __shfl_up_sync(0xffffffffu, xs, off);
        if (lane >= off) xs += n;
    }
    if (lane == 31) wsum[warp] = xs;
    __syncthreads();
    float offacc = 0.f;
    #pragma unroll
    for (int w = 0; w < 4; w++)
        if (w < warp) offacc += wsum[w];
    float cum = offacc + xs - dts;     // exclusive prefix

    float r0 = 0.f, r1 = 0.f, r2 = 0.f;
    if (tid < S_USED) {
        float wgt = expf(cum) * (1.f - expf(dts));
        c0 = fminf(fmaxf(c0 + 0.5f, 0.f), 100000.f);
        c1 = fminf(fmaxf(c1 + 0.5f, 0.f), 100000.f);
        c2 = fminf(fmaxf(c2 + 0.5f, 0.f), 100000.f);
        r0 = wgt * c0;  r1 = wgt * c1;  r2 = wgt * c2;
    }

    #pragma unroll
    for (int off = 16; off > 0; off >>= 1) {
        r0 += __shfl_down_sync(0xffffffffu, r0, off);
        r1 += __shfl_down_sync(0xffffffffu, r1, off);
        r2 += __shfl_down_sync(0xffffffffu, r2, off);
    }
    if (lane == 0) {
        red[warp][0] = r0;  red[warp][1] = r1;  red[warp][2] = r2;
    }
    __syncthreads();
    if (tid == 0) {
        out[ray*3+0] = red[0][0] + red[1][0] + red[2][0] + red[3][0];
        out[ray*3+1] = red[0][1] + red[1][1] + red[2][1] + red[3][1];
        out[ray*3+2] = red[0][2] + red[1][2] + red[2][2] + red[3][2];
    }
}

extern "C" void kernel_launch(void* const* d_in, const int* in_sizes, int n_in,
                              void* d_out, int out_size)
{
    const float* x       = (const float*)d_in[0];
    const float* d       = (const float*)d_in[1];
    const float* tmin    = (const float*)d_in[2];
    const float* tmax    = (const float*)d_in[3];
    const float* grid    = (const float*)d_in[4];
    const float* opacity = (const float*)d_in[5];
    float* out = (float*)d_out;

    rf_render_kernel<<<N_RAYS, 128>>>(x, d, tmin, tmax, grid, opacity, out);
}

// round 6
// speedup vs baseline: 1.2956x; 1.1144x over previous
#include <cuda_runtime.h>
#include <math.h>

#define N_RAYS   32768
#define S_USED   115        // only samples 0..114 contribute
#define GD       128
#define NCH      27

__global__ __launch_bounds__(128, 9)
void rf_render_kernel(const float* __restrict__ xin,
                      const float* __restrict__ din,
                      const float* __restrict__ tminp,
                      const float* __restrict__ tmaxp,
                      const float* __restrict__ grid,
                      const float* __restrict__ opacity,
                      float* __restrict__ out)
{
    __shared__ float coef[S_USED][29];
    __shared__ float shs[9];
    __shared__ float wsum[4];
    __shared__ float red[4][3];

    const int ray  = blockIdx.x;
    const int tid  = threadIdx.x;
    const int lane = tid & 31;
    const int warp = tid >> 5;

    const float dx = din[ray*3+0];
    const float dy = din[ray*3+1];
    const float dz = din[ray*3+2];
    const float ox = xin[ray*3+0];
    const float oy = xin[ray*3+1];
    const float oz = xin[ray*3+2];
    const float t0 = tminp[ray];
    const float range = tmaxp[ray] - t0;

    if (tid < 9) {
        float v = 0.f;
        switch (tid) {
            case 0: v = 0.28209479177387814f; break;
            case 1: v = -0.4886025119029199f * dy; break;
            case 2: v =  0.4886025119029199f * dz; break;
            case 3: v = -0.4886025119029199f * dx; break;
            case 4: v =  1.0925484305920792f * dx * dy; break;
            case 5: v = -1.0925484305920792f * dy * dz; break;
            case 6: v =  0.31539156525252005f * (2.f*dz*dz - dx*dx - dy*dy); break;
            case 7: v = -1.0925484305920792f * dx * dz; break;
            case 8: v =  0.5462742152960396f * (dx*dx - dy*dy); break;
        }
        shs[tid] = v;
    }
    __syncthreads();

    const float mysh = (lane < 27) ? shs[lane % 9] : 1.f;

    // lanes 0..26 -> grid channel `lane`; lanes 27..31 -> opacity (dupes discarded)
    const float* bptr  = (lane < NCH) ? (grid + lane) : opacity;
    const int   stride = (lane < NCH) ? NCH : 1;

    const int s1     = stride;        // z+1
    const int s128   = stride << 7;   // y+1
    const int s16384 = stride << 14;  // x+1
    const int o3 = s128 + s1;
    const int o5 = s16384 + s1;
    const int o6 = s16384 + s128;
    const int o7 = s16384 + s128 + s1;

    // ---- phase 1: contiguous sample chunk per warp; corner-register reuse ----
    const int chunk = (S_USED + 3) / 4;           // 29
    const int sbeg  = warp * chunk;
    const int send  = min(sbeg + chunk, S_USED);

    // incremental ray marching: p(s) = o + t(s)*d,  t(s) = t0 + range*(0.05 + s/128)
    const float step = range * (1.f / 128.f);
    const float tb   = fmaf(range, fmaf((float)sbeg, 1.f/128.f, 0.05f), t0);
    float px = fmaf(tb, dx, ox);
    float py = fmaf(tb, dy, oy);
    float pz = fmaf(tb, dz, oz);
    const float sx = step * dx, sy = step * dy, sz = step * dz;

    float v0, v1, v2, v3, v4, v5, v6, v7;
    v0 = v1 = v2 = v3 = v4 = v5 = v6 = v7 = 0.f;
    int bprev = 0x40000000;   // impossible

    for (int s = sbeg; s < send; s++) {
        float cx = fminf(fmaxf(px, 0.f), 126.9999f);
        float cy = fminf(fmaxf(py, 0.f), 126.9999f);
        float cz = fminf(fmaxf(pz, 0.f), 126.9999f);

        float fx0 = floorf(cx), fy0 = floorf(cy), fz0 = floorf(cz);
        int ix0 = (int)fx0, iy0 = (int)fy0, iz0 = (int)fz0;
        float fx = cx - fx0, fy = cy - fy0, fz = cz - fz0;

        int b = ((ix0 << 14) + (iy0 << 7) + iz0) * stride;

        // warp-uniform predicate (b scales with per-lane stride on both sides)
        if (b != bprev) {
            const float* cell = bptr + b;
            v0 = __ldg(cell);
            v1 = __ldg(cell + s1);
            v2 = __ldg(cell + s128);
            v3 = __ldg(cell + o3);
            v4 = __ldg(cell + s16384);
            v5 = __ldg(cell + o5);
            v6 = __ldg(cell + o6);
            v7 = __ldg(cell + o7);
            bprev = b;
        }

        // factored trilerp: z, then y, then x (7 lerps)
        float c00 = fmaf(fz, v1 - v0, v0);
        float c01 = fmaf(fz, v3 - v2, v2);
        float c10 = fmaf(fz, v5 - v4, v4);
        float c11 = fmaf(fz, v7 - v6, v6);
        float d0  = fmaf(fy, c01 - c00, c00);
        float d1  = fmaf(fy, c11 - c10, c10);
        float acc = fmaf(fx, d1 - d0, d0);

        if (lane < 28)
            coef[s][lane] = acc * mysh;

        px += sx;  py += sy;  pz += sz;
    }
    __syncthreads();

    // ---- phase 2: thread-per-sample dot + transmittance scan + reduce ----
    float dts = 0.f;
    float c0 = 0.f, c1 = 0.f, c2 = 0.f;
    if (tid < S_USED) {
        const float* row = coef[tid];
        #pragma unroll
        for (int j = 0; j < 9; j++) {
            c0 += row[j];
            c1 += row[9 + j];
            c2 += row[18 + j];
        }
        float op = fminf(fmaxf(row[27], 0.f), 100000.f);
        float delta = range * (1.f / 128.f);
        dts = -delta * op;
    }

    float xs = dts;
    #pragma unroll
    for (int off = 1; off < 32; off <<= 1) {
        float n = __shfl_up_sync(0xffffffffu, xs, off);
        if (lane >= off) xs += n;
    }
    if (lane == 31) wsum[warp] = xs;
    __syncthreads();
    float offacc = 0.f;
    #pragma unroll
    for (int w = 0; w < 4; w++)
        if (w < warp) offacc += wsum[w];
    float cum = offacc + xs - dts;     // exclusive prefix

    float r0 = 0.f, r1 = 0.f, r2 = 0.f;
    if (tid < S_USED) {
        float wgt = expf(cum) * (1.f - expf(dts));
        c0 = fminf(fmaxf(c0 + 0.5f, 0.f), 100000.f);
        c1 = fminf(fmaxf(c1 + 0.5f, 0.f), 100000.f);
        c2 = fminf(fmaxf(c2 + 0.5f, 0.f), 100000.f);
        r0 = wgt * c0;  r1 = wgt * c1;  r2 = wgt * c2;
    }

    #pragma unroll
    for (int off = 16; off > 0; off >>= 1) {
        r0 += __shfl_down_sync(0xffffffffu, r0, off);
        r1 += __shfl_down_sync(0xffffffffu, r1, off);
        r2 += __shfl_down_sync(0xffffffffu, r2, off);
    }
    if (lane == 0) {
        red[warp][0] = r0;  red[warp][1] = r1;  red[warp][2] = r2;
    }
    __syncthreads();
    if (tid == 0) {
        out[ray*3+0] = red[0][0] + red[1][0] + red[2][0] + red[3][0];
        out[ray*3+1] = red[0][1] + red[1][1] + red[2][1] + red[3][1];
        out[ray*3+2] = red[0][2] + red[1][2] + red[2][2] + red[3][2];
    }
}

extern "C" void kernel_launch(void* const* d_in, const int* in_sizes, int n_in,
                              void* d_out, int out_size)
{
    const float* x       = (const float*)d_in[0];
    const float* d       = (const float*)d_in[1];
    const float* tmin    = (const float*)d_in[2];
    const float* tmax    = (const float*)d_in[3];
    const float* grid    = (const float*)d_in[4];
    const float* opacity = (const float*)d_in[5];
    float* out = (float*)d_out;

    rf_render_kernel<<<N_RAYS, 128>>>(x, d, tmin, tmax, grid, opacity, out);
}

// round 7
// speedup vs baseline: 1.4083x; 1.0870x over previous
#include <cuda_runtime.h>
#include <math.h>

#define N_RAYS   32768
#define S_USED   115        // only samples 0..114 contribute
#define GD       128
#define NCH      27

__global__ __launch_bounds__(128, 10)
void rf_render_kernel(const float* __restrict__ xin,
                      const float* __restrict__ din,
                      const float* __restrict__ tminp,
                      const float* __restrict__ tmaxp,
                      const float* __restrict__ grid,
                      const float* __restrict__ opacity,
                      float* __restrict__ out)
{
    __shared__ float coef[S_USED][29];
    __shared__ float shs[9];
    __shared__ float wsum[4];
    __shared__ float red[4][3];

    const int ray  = blockIdx.x;
    const int tid  = threadIdx.x;
    const int lane = tid & 31;
    const int warp = tid >> 5;

    const float dx = din[ray*3+0];
    const float dy = din[ray*3+1];
    const float dz = din[ray*3+2];
    const float ox = xin[ray*3+0];
    const float oy = xin[ray*3+1];
    const float oz = xin[ray*3+2];
    const float t0 = tminp[ray];
    const float range = tmaxp[ray] - t0;

    if (tid < 9) {
        float v = 0.f;
        switch (tid) {
            case 0: v = 0.28209479177387814f; break;
            case 1: v = -0.4886025119029199f * dy; break;
            case 2: v =  0.4886025119029199f * dz; break;
            case 3: v = -0.4886025119029199f * dx; break;
            case 4: v =  1.0925484305920792f * dx * dy; break;
            case 5: v = -1.0925484305920792f * dy * dz; break;
            case 6: v =  0.31539156525252005f * (2.f*dz*dz - dx*dx - dy*dy); break;
            case 7: v = -1.0925484305920792f * dx * dz; break;
            case 8: v =  0.5462742152960396f * (dx*dx - dy*dy); break;
        }
        shs[tid] = v;
    }
    __syncthreads();

    const float mysh = (lane < 27) ? shs[lane % 9] : 1.f;

    // lanes 0..26 -> grid channel `lane`; lanes 27..31 -> opacity (dupes discarded)
    const float* bptr  = (lane < NCH) ? (grid + lane) : opacity;
    const int   stride = (lane < NCH) ? NCH : 1;

    const int s1   = stride;          // z+1 (scaled)
    const int s128 = stride << 7;     // y+1 (scaled); x+1 = s128<<7

    // ---- phase 1: contiguous sample chunk per warp; corner-register reuse ----
    const int chunk = (S_USED + 3) / 4;           // 29
    const int sbeg  = warp * chunk;
    const int send  = min(sbeg + chunk, S_USED);

    // incremental ray marching: p(s) = o + t(s)*d,  t(s) = t0 + range*(0.05 + s/128)
    const float step = range * (1.f / 128.f);
    const float tb   = fmaf(range, fmaf((float)sbeg, 1.f/128.f, 0.05f), t0);
    float px = fmaf(tb, dx, ox);
    float py = fmaf(tb, dy, oy);
    float pz = fmaf(tb, dz, oz);
    const float sx = step * dx, sy = step * dy, sz = step * dz;

    float v0, v1, v2, v3, v4, v5, v6, v7;
    v0 = v1 = v2 = v3 = v4 = v5 = v6 = v7 = 0.f;
    int bprev = 0x40000000;   // impossible

    #pragma unroll 2
    for (int s = sbeg; s < send; s++) {
        float cx = fminf(fmaxf(px, 0.f), 126.9999f);
        float cy = fminf(fmaxf(py, 0.f), 126.9999f);
        float cz = fminf(fmaxf(pz, 0.f), 126.9999f);

        float fx0 = floorf(cx), fy0 = floorf(cy), fz0 = floorf(cz);
        int ix0 = (int)fx0, iy0 = (int)fy0, iz0 = (int)fz0;
        float fx = cx - fx0, fy = cy - fy0, fz = cz - fz0;

        int b = ((ix0 << 14) + (iy0 << 7) + iz0) * stride;

        // warp-uniform predicate (b scales with per-lane stride on both sides)
        if (b != bprev) {
            const float* cell = bptr + b;
            const float* cellx = cell + (s128 << 7);   // x+1 plane
            v0 = __ldg(cell);
            v1 = __ldg(cell + s1);
            v2 = __ldg(cell + s128);
            v3 = __ldg(cell + s128 + s1);
            v4 = __ldg(cellx);
            v5 = __ldg(cellx + s1);
            v6 = __ldg(cellx + s128);
            v7 = __ldg(cellx + s128 + s1);
            bprev = b;
        }

        // factored trilerp: z, then y, then x (7 lerps)
        float c00 = fmaf(fz, v1 - v0, v0);
        float c01 = fmaf(fz, v3 - v2, v2);
        float c10 = fmaf(fz, v5 - v4, v4);
        float c11 = fmaf(fz, v7 - v6, v6);
        float d0  = fmaf(fy, c01 - c00, c00);
        float d1  = fmaf(fy, c11 - c10, c10);
        float acc = fmaf(fx, d1 - d0, d0);

        if (lane < 28)
            coef[s][lane] = acc * mysh;

        px += sx;  py += sy;  pz += sz;
    }
    __syncthreads();

    // ---- phase 2: thread-per-sample dot + transmittance scan + reduce ----
    float dts = 0.f;
    float c0 = 0.f, c1 = 0.f, c2 = 0.f;
    if (tid < S_USED) {
        const float* row = coef[tid];
        #pragma unroll
        for (int j = 0; j < 9; j++) {
            c0 += row[j];
            c1 += row[9 + j];
            c2 += row[18 + j];
        }
        float op = fminf(fmaxf(row[27], 0.f), 100000.f);
        float delta = range * (1.f / 128.f);
        dts = -delta * op;
    }

    float xs = dts;
    #pragma unroll
    for (int off = 1; off < 32; off <<= 1) {
        float n = __shfl_up_sync(0xffffffffu, xs, off);
        if (lane >= off) xs += n;
    }
    if (lane == 31) wsum[warp] = xs;
    __syncthreads();
    float offacc = 0.f;
    #pragma unroll
    for (int w = 0; w < 4; w++)
        if (w < warp) offacc += wsum[w];
    float cum = offacc + xs - dts;     // exclusive prefix

    float r0 = 0.f, r1 = 0.f, r2 = 0.f;
    if (tid < S_USED) {
        float wgt = expf(cum) * (1.f - expf(dts));
        c0 = fminf(fmaxf(c0 + 0.5f, 0.f), 100000.f);
        c1 = fminf(fmaxf(c1 + 0.5f, 0.f), 100000.f);
        c2 = fminf(fmaxf(c2 + 0.5f, 0.f), 100000.f);
        r0 = wgt * c0;  r1 = wgt * c1;  r2 = wgt * c2;
    }

    #pragma unroll
    for (int off = 16; off > 0; off >>= 1) {
        r0 += __shfl_down_sync(0xffffffffu, r0, off);
        r1 += __shfl_down_sync(0xffffffffu, r1, off);
        r2 += __shfl_down_sync(0xffffffffu, r2, off);
    }
    if (lane == 0) {
        red[warp][0] = r0;  red[warp][1] = r1;  red[warp][2] = r2;
    }
    __syncthreads();
    if (tid == 0) {
        out[ray*3+0] = red[0][0] + red[1][0] + red[2][0] + red[3][0];
        out[ray*3+1] = red[0][1] + red[1][1] + red[2][1] + red[3][1];
        out[ray*3+2] = red[0][2] + red[1][2] + red[2][2] + red[3][2];
    }
}

extern "C" void kernel_launch(void* const* d_in, const int* in_sizes, int n_in,
                              void* d_out, int out_size)
{
    const float* x       = (const float*)d_in[0];
    const float* d       = (const float*)d_in[1];
    const float* tmin    = (const float*)d_in[2];
    const float* tmax    = (const float*)d_in[3];
    const float* grid    = (const float*)d_in[4];
    const float* opacity = (const float*)d_in[5];
    float* out = (float*)d_out;

    rf_render_kernel<<<N_RAYS, 128>>>(x, d, tmin, tmax, grid, opacity, out);
}

// round 8
// speedup vs baseline: 1.4788x; 1.0500x over previous
#include <cuda_runtime.h>
#include <math.h>

#define N_RAYS   32768
#define S_USED   115        // only samples 0..114 contribute
#define GD       128
#define NCH      27

__global__ __launch_bounds__(128, 11)
void rf_render_kernel(const float* __restrict__ xin,
                      const float* __restrict__ din,
                      const float* __restrict__ tminp,
                      const float* __restrict__ tmaxp,
                      const float* __restrict__ grid,
                      const float* __restrict__ opacity,
                      float* __restrict__ out)
{
    __shared__ float coef[S_USED][29];
    __shared__ float shs[9];
    __shared__ float wsum[4];
    __shared__ float red[4][3];

    const int ray  = blockIdx.x;
    const int tid  = threadIdx.x;
    const int lane = tid & 31;
    const int warp = tid >> 5;

    const float dx = din[ray*3+0];
    const float dy = din[ray*3+1];
    const float dz = din[ray*3+2];
    const float ox = xin[ray*3+0];
    const float oy = xin[ray*3+1];
    const float oz = xin[ray*3+2];
    const float t0 = tminp[ray];
    const float range = tmaxp[ray] - t0;

    if (tid < 9) {
        float v = 0.f;
        switch (tid) {
            case 0: v = 0.28209479177387814f; break;
            case 1: v = -0.4886025119029199f * dy; break;
            case 2: v =  0.4886025119029199f * dz; break;
            case 3: v = -0.4886025119029199f * dx; break;
            case 4: v =  1.0925484305920792f * dx * dy; break;
            case 5: v = -1.0925484305920792f * dy * dz; break;
            case 6: v =  0.31539156525252005f * (2.f*dz*dz - dx*dx - dy*dy); break;
            case 7: v = -1.0925484305920792f * dx * dz; break;
            case 8: v =  0.5462742152960396f * (dx*dx - dy*dy); break;
        }
        shs[tid] = v;
    }
    __syncthreads();

    const float mysh = (lane < 27) ? shs[lane % 9] : 1.f;

    // lanes 0..26 -> grid channel `lane`; lanes 27..31 -> opacity (dupes discarded)
    const float* bptr  = (lane < NCH) ? (grid + lane) : opacity;
    const int   stride = (lane < NCH) ? NCH : 1;

    const int s1   = stride;          // z+1 (scaled)
    const int s128 = stride << 7;     // y+1 (scaled); x+1 = s128<<7

    // ---- phase 1: contiguous sample chunk per warp; corner-register reuse ----
    const int chunk = (S_USED + 3) / 4;           // 29
    const int sbeg  = warp * chunk;
    const int send  = min(sbeg + chunk, S_USED);

    // incremental ray marching
    const float step = range * (1.f / 128.f);
    const float tb   = fmaf(range, fmaf((float)sbeg, 1.f/128.f, 0.05f), t0);
    float px = fmaf(tb, dx, ox);
    float py = fmaf(tb, dy, oy);
    float pz = fmaf(tb, dz, oz);
    const float sx = step * dx, sy = step * dy, sz = step * dz;

    float v0, v1, v2, v3, v4, v5, v6, v7;
    v0 = v1 = v2 = v3 = v4 = v5 = v6 = v7 = 0.f;
    float Bprev = -1.f;    // impossible cell id

    #pragma unroll 2
    for (int s = sbeg; s < send; s++) {
        float cx = fminf(fmaxf(px, 0.f), 126.9999f);
        float cy = fminf(fmaxf(py, 0.f), 126.9999f);
        float cz = fminf(fmaxf(pz, 0.f), 126.9999f);

        float fx0 = floorf(cx), fy0 = floorf(cy), fz0 = floorf(cz);
        float fx = cx - fx0, fy = cy - fy0, fz = cz - fz0;

        // float cell id: exact (integer-valued, < 2^24)
        float B = fmaf(fy0, 128.f, fmaf(fx0, 16384.f, fz0));

        // warp-uniform predicate (identical across lanes)
        if (B != Bprev) {
            int b = (int)B * stride;
            const float* cell  = bptr + b;
            const float* cellx = cell + (s128 << 7);   // x+1 plane
            v0 = __ldg(cell);
            v1 = __ldg(cell + s1);
            v2 = __ldg(cell + s128);
            v3 = __ldg(cell + s128 + s1);
            v4 = __ldg(cellx);
            v5 = __ldg(cellx + s1);
            v6 = __ldg(cellx + s128);
            v7 = __ldg(cellx + s128 + s1);
            Bprev = B;
        }

        // factored trilerp: z, then y, then x (7 lerps)
        float c00 = fmaf(fz, v1 - v0, v0);
        float c01 = fmaf(fz, v3 - v2, v2);
        float c10 = fmaf(fz, v5 - v4, v4);
        float c11 = fmaf(fz, v7 - v6, v6);
        float d0  = fmaf(fy, c01 - c00, c00);
        float d1  = fmaf(fy, c11 - c10, c10);
        float acc = fmaf(fx, d1 - d0, d0);

        if (lane < 28)
            coef[s][lane] = acc * mysh;

        px += sx;  py += sy;  pz += sz;
    }
    __syncthreads();

    // ---- phase 2: thread-per-sample dot + transmittance scan + reduce ----
    float dts = 0.f;
    float c0 = 0.f, c1 = 0.f, c2 = 0.f;
    if (tid < S_USED) {
        const float* row = coef[tid];
        #pragma unroll
        for (int j = 0; j < 9; j++) {
            c0 += row[j];
            c1 += row[9 + j];
            c2 += row[18 + j];
        }
        float op = fminf(fmaxf(row[27], 0.f), 100000.f);
        float delta = range * (1.f / 128.f);
        dts = -delta * op;
    }

    float xs = dts;
    #pragma unroll
    for (int off = 1; off < 32; off <<= 1) {
        float n = __shfl_up_sync(0xffffffffu, xs, off);
        if (lane >= off) xs += n;
    }
    if (lane == 31) wsum[warp] = xs;
    __syncthreads();
    float offacc = 0.f;
    #pragma unroll
    for (int w = 0; w < 4; w++)
        if (w < warp) offacc += wsum[w];
    float cum = offacc + xs - dts;     // exclusive prefix

    float r0 = 0.f, r1 = 0.f, r2 = 0.f;
    if (tid < S_USED) {
        float wgt = expf(cum) * (1.f - expf(dts));
        c0 = fminf(fmaxf(c0 + 0.5f, 0.f), 100000.f);
        c1 = fminf(fmaxf(c1 + 0.5f, 0.f), 100000.f);
        c2 = fminf(fmaxf(c2 + 0.5f, 0.f), 100000.f);
        r0 = wgt * c0;  r1 = wgt * c1;  r2 = wgt * c2;
    }

    #pragma unroll
    for (int off = 16; off > 0; off >>= 1) {
        r0 += __shfl_down_sync(0xffffffffu, r0, off);
        r1 += __shfl_down_sync(0xffffffffu, r1, off);
        r2 += __shfl_down_sync(0xffffffffu, r2, off);
    }
    if (lane == 0) {
        red[warp][0] = r0;  red[warp][1] = r1;  red[warp][2] = r2;
    }
    __syncthreads();
    if (tid == 0) {
        out[ray*3+0] = red[0][0] + red[1][0] + red[2][0] + red[3][0];
        out[ray*3+1] = red[0][1] + red[1][1] + red[2][1] + red[3][1];
        out[ray*3+2] = red[0][2] + red[1][2] + red[2][2] + red[3][2];
    }
}

extern "C" void kernel_launch(void* const* d_in, const int* in_sizes, int n_in,
                              void* d_out, int out_size)
{
    const float* x       = (const float*)d_in[0];
    const float* d       = (const float*)d_in[1];
    const float* tmin    = (const float*)d_in[2];
    const float* tmax    = (const float*)d_in[3];
    const float* grid    = (const float*)d_in[4];
    const float* opacity = (const float*)d_in[5];
    float* out = (float*)d_out;

    rf_render_kernel<<<N_RAYS, 128>>>(x, d, tmin, tmax, grid, opacity, out);
}